// round 13
// baseline (speedup 1.0000x reference)
#include <cuda_runtime.h>
#include <cuda_fp16.h>
#include <cstdint>

#define TOKENS   200704      // 4096 * 49
#define DIMC     512
#define QKV_N    1536
#define KDIM     512
#define SS       49
#define NHEADS   16
#define HD       32
#define NWG      64

// ---------------- scratch ---------------------------------------------------
__device__ __half g_qkvh[(size_t)TOKENS * QKV_N];    // 617 MB fp16 qkv
__device__ __half g_xh[(size_t)TOKENS * KDIM];       // fp16 activations (reused for attn out)
__device__ __half g_wqh[(size_t)QKV_N * KDIM];       // Wqkv^T fp16
__device__ __half g_wph[(size_t)DIMC * KDIM];        // Wproj^T fp16
__device__ __half g_comb2[(size_t)NWG * NHEADS * 64 * 56];  // (bias+mask)*log2e fp16, padded

// ---------------- asm helpers -----------------------------------------------
__device__ __forceinline__ uint32_t smem_u32(const void* p) {
    uint32_t a;
    asm("{ .reg .u64 t; cvta.to.shared.u64 t, %1; cvt.u32.u64 %0, t; }" : "=r"(a) : "l"(p));
    return a;
}

#define CP16(d, s) asm volatile("cp.async.cg.shared.global [%0], [%1], 16;" :: "r"(d), "l"(s))
#define CP_COMMIT() asm volatile("cp.async.commit_group;" ::: "memory")
#define CP_WAIT2()  asm volatile("cp.async.wait_group 2;" ::: "memory")
#define CP_WAIT1()  asm volatile("cp.async.wait_group 1;" ::: "memory")
#define CP_WAIT0()  asm volatile("cp.async.wait_group 0;" ::: "memory")

#define LDSM4(R, a) asm volatile( \
    "ldmatrix.sync.aligned.m8n8.x4.shared.b16 {%0,%1,%2,%3}, [%4];" \
    : "=r"((R)[0]),"=r"((R)[1]),"=r"((R)[2]),"=r"((R)[3]) : "r"(a))
#define LDSM2(R, a) asm volatile( \
    "ldmatrix.sync.aligned.m8n8.x2.shared.b16 {%0,%1}, [%2];" \
    : "=r"((R)[0]),"=r"((R)[1]) : "r"(a))

#define MMA16816(Cc, Aa, Bb) asm volatile( \
    "mma.sync.aligned.m16n8k16.row.col.f32.f16.f16.f32 " \
    "{%0,%1,%2,%3}, {%4,%5,%6,%7}, {%8,%9}, {%0,%1,%2,%3};" \
    : "+f"((Cc)[0]),"+f"((Cc)[1]),"+f"((Cc)[2]),"+f"((Cc)[3]) \
    : "r"((Aa)[0]),"r"((Aa)[1]),"r"((Aa)[2]),"r"((Aa)[3]), "r"((Bb)[0]),"r"((Bb)[1]))

// ex2 on two packed halves in one MUFU op
#define EX2F16X2(r, x) asm("ex2.approx.f16x2 %0, %1;" : "=r"(r) : "r"(x))

__device__ __forceinline__ uint32_t h2u(float a, float b) {
    __half2 t = __floats2half2_rn(a, b);
    return reinterpret_cast<uint32_t&>(t);
}

// ---------------- convert kernels --------------------------------------------
__global__ __launch_bounds__(256) void conv_x(const float* __restrict__ in,
                                              __half* __restrict__ oh)
{
    size_t base = ((size_t)blockIdx.x * 256 + threadIdx.x) * 4;
    float4 f = *(const float4*)(in + base);
    __half2 h2[2] = { __halves2half2(__float2half_rn(f.x), __float2half_rn(f.y)),
                      __halves2half2(__float2half_rn(f.z), __float2half_rn(f.w)) };
    *(uint2*)(oh + base) = *(uint2*)h2;
}

__global__ __launch_bounds__(256) void conv_w(const float* __restrict__ in,
                                              __half* __restrict__ oh, int K, int N)
{
    int t = blockIdx.x * 256 + threadIdx.x;
    if (t >= K * N) return;
    int k = t / N, n = t - k * N;
    oh[(size_t)n * K + k] = __float2half_rn(in[t]);   // W^T layout [n][k]
}

// ---------------- comb2 = fp16 padded (bias+mask)*log2e -----------------------
__global__ __launch_bounds__(256) void comb_k(const float* __restrict__ mask,
                                              const float* __restrict__ bias_table,
                                              const int* __restrict__ rel_index,
                                              __half* __restrict__ comb)
{
    int idx = blockIdx.x * 256 + threadIdx.x;
    const int total = NWG * NHEADS * 64 * 56;
    if (idx >= total) return;
    int c = idx % 56;
    int t = idx / 56;
    int r = t % 64;  t /= 64;
    int h = t % NHEADS;
    int g = t / NHEADS;
    float v;
    if (c >= SS)      v = -20000.f;
    else if (r >= SS) v = 0.f;
    else v = bias_table[rel_index[r * SS + c] * NHEADS + h] + mask[((size_t)g * SS + r) * SS + c];
    comb[idx] = __float2half_rn(v * 1.4426950408889634f);
}

// ---------------- HMMA fp16 GEMM ----------------------------------------------
// C[M,N] = A[M,512] @ B[N,512]^T + bias (fp32 accum)
// Block 128x256, warp tile 64x64 (2x4 warp grid), BK=64, 4-stage cp.async.
// out_mode 0: fp32 out; 1: fp16 out, cols<512 scaled by hd^-0.5 * log2e (q in log2 units)
#define STAGE_BYTES 49152          // A 16 KB + B 32 KB
#define GEMM_SMEM   (4 * STAGE_BYTES)

__global__ __launch_bounds__(256, 1) void gemm_hmma(
    const __half* __restrict__ Ahp, const __half* __restrict__ Bhp,
    const float* __restrict__ bias, void* __restrict__ Cv, int N, int out_mode)
{
    extern __shared__ char smem[];
    const uint32_t sb = smem_u32(smem);
    const int tid = threadIdx.x, wid = tid >> 5, lane = tid & 31;
    const int m0 = blockIdx.y * 128, n0 = blockIdx.x * 256;
    const int warp_m = wid & 1, warp_n = wid >> 1;

    float acc[4][8][4];
#pragma unroll
    for (int a = 0; a < 4; a++)
#pragma unroll
        for (int b = 0; b < 8; b++)
#pragma unroll
            for (int c = 0; c < 4; c++) acc[a][b][c] = 0.f;

    const int cr0 = tid >> 3;        // 0..31
    const int ckc = tid & 7;         // 16B chunk within 128B row

#define LOAD_STAGE(st, ch) do {                                              \
        uint32_t sp_ = sb + (st) * STAGE_BYTES;                              \
        int kt_ = (ch) * 64;                                                 \
        size_t so_ = (size_t)kt_ + ckc * 8;                                  \
        _Pragma("unroll")                                                    \
        for (int u = 0; u < 4; u++) {                                        \
            int r_ = cr0 + u * 32;                                           \
            uint32_t d_ = sp_ + r_ * 128 + (((uint32_t)(ckc ^ (r_ & 7))) << 4); \
            CP16(d_, Ahp + (size_t)(m0 + r_) * KDIM + so_);                  \
        }                                                                    \
        _Pragma("unroll")                                                    \
        for (int u = 0; u < 8; u++) {                                        \
            int r_ = cr0 + u * 32;                                           \
            uint32_t d_ = sp_ + 16384 + r_ * 128 + (((uint32_t)(ckc ^ (r_ & 7))) << 4); \
            CP16(d_, Bhp + (size_t)(n0 + r_) * KDIM + so_);                  \
        }                                                                    \
    } while (0)

    LOAD_STAGE(0, 0); CP_COMMIT();
    LOAD_STAGE(1, 1); CP_COMMIT();
    LOAD_STAGE(2, 2); CP_COMMIT();

    const int g  = lane >> 3;
    const int lr = lane & 7;
    const int gh = g >> 1;
    const int lrB = lane & 7, hB = (lane >> 3) & 1;
    const uint32_t aRow = (uint32_t)((warp_m * 64 + (g & 1) * 8 + lr) * 128);
    const uint32_t bRow = (uint32_t)((warp_n * 64 + lrB) * 128);

    for (int c = 0; c < 8; c++) {
        if (c < 6) CP_WAIT2(); else if (c == 6) CP_WAIT1(); else CP_WAIT0();
        __syncthreads();
        if (c + 3 < 8) { LOAD_STAGE((c + 3) & 3, c + 3); CP_COMMIT(); }

        const uint32_t As = sb + (c & 3) * STAGE_BYTES;
        const uint32_t Bs = As + 16384;
#pragma unroll
        for (int ks = 0; ks < 4; ks++) {
            uint32_t ah[4][4], bh[8][2];
            const uint32_t cA = (uint32_t)(((ks * 2 + gh) ^ lr) << 4);
            const uint32_t cB = (uint32_t)(((ks * 2 + hB) ^ lrB) << 4);
#pragma unroll
            for (int mi = 0; mi < 4; mi++) LDSM4(ah[mi], As + aRow + mi * 2048 + cA);
#pragma unroll
            for (int ni = 0; ni < 8; ni++) LDSM2(bh[ni], Bs + bRow + ni * 1024 + cB);
#pragma unroll
            for (int mi = 0; mi < 4; mi++)
#pragma unroll
                for (int ni = 0; ni < 8; ni++) MMA16816(acc[mi][ni], ah[mi], bh[ni]);
        }
    }

    const int rbase = m0 + warp_m * 64 + (lane >> 2);
    const int cbase = n0 + warp_n * 64 + (lane & 3) * 2;
    if (out_mode == 0) {
        float* C = (float*)Cv;
#pragma unroll
        for (int mi = 0; mi < 4; mi++)
#pragma unroll
            for (int ni = 0; ni < 8; ni++) {
                int cc = cbase + ni * 8;
                float b0 = bias[cc], b1 = bias[cc + 1];
                int r0 = rbase + mi * 16;
                *(float2*)(C + (size_t)r0 * N + cc) =
                    make_float2(acc[mi][ni][0] + b0, acc[mi][ni][1] + b1);
                *(float2*)(C + (size_t)(r0 + 8) * N + cc) =
                    make_float2(acc[mi][ni][2] + b0, acc[mi][ni][3] + b1);
            }
    } else {
        __half* C = (__half*)Cv;
#pragma unroll
        for (int mi = 0; mi < 4; mi++)
#pragma unroll
            for (int ni = 0; ni < 8; ni++) {
                int cc = cbase + ni * 8;
                // q columns carry hd^-0.5 * log2e (attention works in log2 domain)
                const float s = (cc < 512) ? (0.17677669529663687f * 1.4426950408889634f) : 1.0f;
                float b0 = bias[cc], b1 = bias[cc + 1];
                int r0 = rbase + mi * 16;
                __half2 w0 = __floats2half2_rn((acc[mi][ni][0] + b0) * s, (acc[mi][ni][1] + b1) * s);
                __half2 w1 = __floats2half2_rn((acc[mi][ni][2] + b0) * s, (acc[mi][ni][3] + b1) * s);
                *(__half2*)(C + (size_t)r0 * N + cc) = w0;
                *(__half2*)(C + (size_t)(r0 + 8) * N + cc) = w1;
            }
    }
#undef LOAD_STAGE
}

// ---------------- tensor-core fused window attention --------------------------
// block: one window x 2 heads; 8 warps; warp = (head hh, m-tile mi)
// softmax in log2 domain via ex2.approx.f16x2; row sums via ones-column of V.
__global__ __launch_bounds__(256) void attn_tc(
    const __half* __restrict__ qkv, const __half* __restrict__ comb2,
    __half* __restrict__ outh)
{
    __shared__ __align__(16) __half sQ[2][64][40];
    __shared__ __align__(16) __half sK[2][64][40];
    __shared__ __align__(16) __half sVt[2][40][72];   // dims 0-31 = V^T, dim 32 = ones

    const int b = blockIdx.x;
    const int h0 = blockIdx.y * 2;
    const int tid = threadIdx.x;
    const int lane = tid & 31, wid = tid >> 5;

    const __half2 zero2 = __halves2half2(__ushort_as_half(0), __ushort_as_half(0));

    // load Q, K [64 rows pad][32] fp16 as half2
#pragma unroll
    for (int u = 0; u < 16; u++) {
        int i = tid + u * 256;
        int d2 = i & 15, row = (i >> 4) & 63, mat = (i >> 10) & 1, hh = i >> 11;
        __half2 v = zero2;
        if (row < SS)
            v = *(const __half2*)(qkv + (size_t)(b * SS + row) * QKV_N
                                  + mat * 512 + (h0 + hh) * HD + d2 * 2);
        if (mat == 0) *(__half2*)&sQ[hh][row][d2 * 2] = v;
        else          *(__half2*)&sK[hh][row][d2 * 2] = v;
    }
    // load V transposed: sVt[hh][dim][token]
#pragma unroll
    for (int u = 0; u < 8; u++) {
        int i = tid + u * 256;
        int d2 = i & 15, row = (i >> 4) & 63, hh = i >> 10;
        __half2 v = zero2;
        if (row < SS)
            v = *(const __half2*)(qkv + (size_t)(b * SS + row) * QKV_N
                                  + 1024 + (h0 + hh) * HD + d2 * 2);
        sVt[hh][d2 * 2][row]     = __low2half(v);
        sVt[hh][d2 * 2 + 1][row] = __high2half(v);
    }
    // ones-column rows (dims 32..39): dim 32 = 1, rest 0
#pragma unroll
    for (int u = 0; u < 4; u++) {
        int i = tid + u * 256;          // 2 heads * 8 dims * 64 tokens = 1024
        int tok = i & 63, d = (i >> 6) & 7, hh = i >> 9;
        sVt[hh][32 + d][tok] = (d == 0) ? __float2half(1.f) : __ushort_as_half(0);
    }
    __syncthreads();

    const int hh = wid >> 2;
    const int mi = wid & 3;
    const int h  = h0 + hh;
    const int lr = lane & 7;
    const int grp = lane >> 3;
    const int khalf = (lane >> 3) & 1;

    // Q A-fragments (2 k16 tiles)
    uint32_t aq[2][4];
    {
        int arow = mi * 16 + (grp & 1) * 8 + lr;
        int acol = (grp >> 1) * 8;
        LDSM4(aq[0], smem_u32(&sQ[hh][arow][acol]));
        LDSM4(aq[1], smem_u32(&sQ[hh][arow][16 + acol]));
    }

    // S = Q K^T  (7 n-tiles), logits in log2 units (q pre-scaled)
    float sacc[7][4];
#pragma unroll
    for (int n = 0; n < 7; n++)
#pragma unroll
        for (int e = 0; e < 4; e++) sacc[n][e] = 0.f;

#pragma unroll
    for (int n = 0; n < 7; n++) {
        int brow = n * 8 + lr;
#pragma unroll
        for (int kt = 0; kt < 2; kt++) {
            uint32_t bk[2];
            LDSM2(bk, smem_u32(&sK[hh][brow][kt * 16 + khalf * 8]));
            MMA16816(sacc[n], aq[kt], bk);
        }
    }

    // add comb (already log2-scaled), then p = 2^s via f16x2 ex2
    const int wg = b & (NWG - 1);
    const __half* cbp = comb2 + (size_t)(wg * NHEADS + h) * 64 * 56;
    const int r0 = mi * 16 + (lane >> 2);
    const int c0 = (lane & 3) * 2;
#pragma unroll
    for (int n = 0; n < 7; n++) {
        __half2 cv0 = *(const __half2*)(cbp + r0 * 56 + n * 8 + c0);
        __half2 cv1 = *(const __half2*)(cbp + (r0 + 8) * 56 + n * 8 + c0);
        float2 f0 = __half22float2(cv0), f1 = __half22float2(cv1);
        sacc[n][0] += f0.x;
        sacc[n][1] += f0.y;
        sacc[n][2] += f1.x;
        sacc[n][3] += f1.y;
    }

    // P -> A fragments directly (unnormalized exps in fp16)
    uint32_t pa[4][4];
#pragma unroll
    for (int t = 0; t < 3; t++) {
        EX2F16X2(pa[t][0], h2u(sacc[2 * t][0],     sacc[2 * t][1]));
        EX2F16X2(pa[t][1], h2u(sacc[2 * t][2],     sacc[2 * t][3]));
        EX2F16X2(pa[t][2], h2u(sacc[2 * t + 1][0], sacc[2 * t + 1][1]));
        EX2F16X2(pa[t][3], h2u(sacc[2 * t + 1][2], sacc[2 * t + 1][3]));
    }
    EX2F16X2(pa[3][0], h2u(sacc[6][0], sacc[6][1]));
    EX2F16X2(pa[3][1], h2u(sacc[6][2], sacc[6][3]));
    pa[3][2] = 0u;
    pa[3][3] = 0u;

    // O = P V  (nv=4 tile holds the ones-column -> row sums in col 32)
    float oacc[5][4];
#pragma unroll
    for (int nv = 0; nv < 5; nv++)
#pragma unroll
        for (int e = 0; e < 4; e++) oacc[nv][e] = 0.f;

#pragma unroll
    for (int t = 0; t < 4; t++)
#pragma unroll
        for (int nv = 0; nv < 5; nv++) {
            uint32_t bv[2];
            LDSM2(bv, smem_u32(&sVt[hh][nv * 8 + lr][t * 16 + khalf * 8]));
            MMA16816(oacc[nv], pa[t], bv);
        }

    // row sums live in col 32 -> quad leader's oacc[4][0]/[2]
    const float rsA = __shfl_sync(0xffffffffu, oacc[4][0], lane & ~3);
    const float rsB = __shfl_sync(0xffffffffu, oacc[4][2], lane & ~3);
    const float inv0 = 1.f / (rsA + 1e-30f);
    const float inv1 = 1.f / (rsB + 1e-30f);

    // store fp16 rows < 49
#pragma unroll
    for (int nv = 0; nv < 4; nv++) {
        int col = h * HD + nv * 8 + c0;
        if (r0 < SS) {
            __half2 w = __floats2half2_rn(oacc[nv][0] * inv0, oacc[nv][1] * inv0);
            *(__half2*)(outh + (size_t)(b * SS + r0) * DIMC + col) = w;
        }
        if (r0 + 8 < SS) {
            __half2 w = __floats2half2_rn(oacc[nv][2] * inv1, oacc[nv][3] * inv1);
            *(__half2*)(outh + (size_t)(b * SS + r0 + 8) * DIMC + col) = w;
        }
    }
}

// ---------------- launch ------------------------------------------------------
extern "C" void kernel_launch(void* const* d_in, const int* in_sizes, int n_in,
                              void* d_out, int out_size)
{
    const float* x          = (const float*)d_in[0];
    const float* mask       = (const float*)d_in[1];
    const float* Wqkv       = (const float*)d_in[2];
    const float* bqkv       = (const float*)d_in[3];
    const float* Wproj      = (const float*)d_in[4];
    const float* bproj      = (const float*)d_in[5];
    const float* bias_table = (const float*)d_in[6];
    const int*   rel_index  = (const int*)d_in[7];
    float* out = (float*)d_out;

    __half *qkvh, *xh, *wqh, *wph, *comb2;
    cudaGetSymbolAddress((void**)&qkvh,  g_qkvh);
    cudaGetSymbolAddress((void**)&xh,    g_xh);
    cudaGetSymbolAddress((void**)&wqh,   g_wqh);
    cudaGetSymbolAddress((void**)&wph,   g_wph);
    cudaGetSymbolAddress((void**)&comb2, g_comb2);

    cudaFuncSetAttribute(gemm_hmma, cudaFuncAttributeMaxDynamicSharedMemorySize, GEMM_SMEM);

    conv_x<<<(size_t)TOKENS * KDIM / 1024, 256>>>(x, xh);
    conv_w<<<(KDIM * QKV_N + 255) / 256, 256>>>(Wqkv, wqh, KDIM, QKV_N);
    conv_w<<<(KDIM * DIMC  + 255) / 256, 256>>>(Wproj, wph, KDIM, DIMC);
    comb_k<<<(NWG * NHEADS * 64 * 56 + 255) / 256, 256>>>(mask, bias_table, rel_index, comb2);

    gemm_hmma<<<dim3(QKV_N / 256, TOKENS / 128), 256, GEMM_SMEM>>>(
        xh, wqh, bqkv, qkvh, QKV_N, 1);

    attn_tc<<<dim3(4096, 8), 256>>>(qkvh, comb2, xh);

    gemm_hmma<<<dim3(DIMC / 256, TOKENS / 128), 256, GEMM_SMEM>>>(
        xh, wph, bproj, out, DIMC, 0);
}

// round 14
// speedup vs baseline: 1.0105x; 1.0105x over previous
#include <cuda_runtime.h>
#include <cuda_fp16.h>
#include <cstdint>

#define TOKENS   200704      // 4096 * 49
#define DIMC     512
#define QKV_N    1536
#define KDIM     512
#define SS       49
#define NHEADS   16
#define HD       32
#define NWG      64

// ---------------- scratch ---------------------------------------------------
__device__ __half g_qkvh[(size_t)TOKENS * QKV_N];    // 617 MB fp16 qkv
__device__ __half g_xh[(size_t)TOKENS * KDIM];       // fp16 attn output
__device__ __half g_wqh[(size_t)QKV_N * KDIM];       // Wqkv^T fp16
__device__ __half g_wph[(size_t)DIMC * KDIM];        // Wproj^T fp16
__device__ __half g_comb2[(size_t)NWG * NHEADS * 64 * 56];  // (bias+mask)*log2e fp16

// ---------------- asm helpers -----------------------------------------------
__device__ __forceinline__ uint32_t smem_u32(const void* p) {
    uint32_t a;
    asm("{ .reg .u64 t; cvta.to.shared.u64 t, %1; cvt.u32.u64 %0, t; }" : "=r"(a) : "l"(p));
    return a;
}

#define CP16(d, s) asm volatile("cp.async.cg.shared.global [%0], [%1], 16;" :: "r"(d), "l"(s))
#define CP_COMMIT() asm volatile("cp.async.commit_group;" ::: "memory")
#define CP_WAIT2()  asm volatile("cp.async.wait_group 2;" ::: "memory")
#define CP_WAIT1()  asm volatile("cp.async.wait_group 1;" ::: "memory")
#define CP_WAIT0()  asm volatile("cp.async.wait_group 0;" ::: "memory")

#define LDSM4(R, a) asm volatile( \
    "ldmatrix.sync.aligned.m8n8.x4.shared.b16 {%0,%1,%2,%3}, [%4];" \
    : "=r"((R)[0]),"=r"((R)[1]),"=r"((R)[2]),"=r"((R)[3]) : "r"(a))
#define LDSM2(R, a) asm volatile( \
    "ldmatrix.sync.aligned.m8n8.x2.shared.b16 {%0,%1}, [%2];" \
    : "=r"((R)[0]),"=r"((R)[1]) : "r"(a))

#define MMA16816(Cc, Aa, Bb) asm volatile( \
    "mma.sync.aligned.m16n8k16.row.col.f32.f16.f16.f32 " \
    "{%0,%1,%2,%3}, {%4,%5,%6,%7}, {%8,%9}, {%0,%1,%2,%3};" \
    : "+f"((Cc)[0]),"+f"((Cc)[1]),"+f"((Cc)[2]),"+f"((Cc)[3]) \
    : "r"((Aa)[0]),"r"((Aa)[1]),"r"((Aa)[2]),"r"((Aa)[3]), "r"((Bb)[0]),"r"((Bb)[1]))

#define EX2F16X2(r, x) asm("ex2.approx.f16x2 %0, %1;" : "=r"(r) : "r"(x))

__device__ __forceinline__ uint32_t h2u(float a, float b) {
    __half2 t = __floats2half2_rn(a, b);
    return reinterpret_cast<uint32_t&>(t);
}

// ---------------- convert / table kernels -------------------------------------
__global__ __launch_bounds__(256) void conv_w(const float* __restrict__ in,
                                              __half* __restrict__ oh, int K, int N)
{
    int t = blockIdx.x * 256 + threadIdx.x;
    if (t >= K * N) return;
    int k = t / N, n = t - k * N;
    oh[(size_t)n * K + k] = __float2half_rn(in[t]);   // W^T layout [n][k]
}

__global__ __launch_bounds__(256) void comb_k(const float* __restrict__ mask,
                                              const float* __restrict__ bias_table,
                                              const int* __restrict__ rel_index,
                                              __half* __restrict__ comb)
{
    int idx = blockIdx.x * 256 + threadIdx.x;
    const int total = NWG * NHEADS * 64 * 56;
    if (idx >= total) return;
    int c = idx % 56;
    int t = idx / 56;
    int r = t % 64;  t /= 64;
    int h = t % NHEADS;
    int g = t / NHEADS;
    float v;
    if (c >= SS)      v = -20000.f;
    else if (r >= SS) v = 0.f;
    else v = bias_table[rel_index[r * SS + c] * NHEADS + h] + mask[((size_t)g * SS + r) * SS + c];
    comb[idx] = __float2half_rn(v * 1.4426950408889634f);
}

// ---------------- HMMA fp16 GEMM ----------------------------------------------
// C[M,N] = A[M,512] @ B[N,512]^T + bias (fp32 accum)
// Block 128x256, warp tile 64x64, BK=64, 4-stage cp.async (B; A via cp.async or
// fused fp32->fp16 LDG/STS when A_FP32=1).
#define STAGE_BYTES 49152          // A 16 KB + B 32 KB
#define GEMM_SMEM   (4 * STAGE_BYTES)

template<int A_FP32>
__global__ __launch_bounds__(256, 1) void gemm_hmma(
    const void* __restrict__ Ap, const __half* __restrict__ Bhp,
    const float* __restrict__ bias, void* __restrict__ Cv, int N, int out_mode)
{
    extern __shared__ char smem[];
    const uint32_t sb = smem_u32(smem);
    const int tid = threadIdx.x, wid = tid >> 5, lane = tid & 31;
    const int m0 = blockIdx.y * 128, n0 = blockIdx.x * 256;
    const int warp_m = wid & 1, warp_n = wid >> 1;

    const int cr0 = tid >> 3;        // 0..31
    const int ckc = tid & 7;         // 16B chunk within 128B row

#define LOAD_B(st, ch) do {                                                  \
        uint32_t spB_ = sb + (st) * STAGE_BYTES + 16384;                     \
        size_t soB_ = (size_t)((ch) * 64) + ckc * 8;                         \
        _Pragma("unroll")                                                    \
        for (int u = 0; u < 8; u++) {                                        \
            int r_ = cr0 + u * 32;                                           \
            uint32_t d_ = spB_ + r_ * 128 + (((uint32_t)(ckc ^ (r_ & 7))) << 4); \
            CP16(d_, Bhp + (size_t)(n0 + r_) * KDIM + soB_);                 \
        }                                                                    \
    } while (0)

#define LOAD_A16(st, ch) do {                                                \
        uint32_t spA_ = sb + (st) * STAGE_BYTES;                             \
        size_t soA_ = (size_t)((ch) * 64) + ckc * 8;                         \
        const __half* Ah_ = (const __half*)Ap;                               \
        _Pragma("unroll")                                                    \
        for (int u = 0; u < 4; u++) {                                        \
            int r_ = cr0 + u * 32;                                           \
            uint32_t d_ = spA_ + r_ * 128 + (((uint32_t)(ckc ^ (r_ & 7))) << 4); \
            CP16(d_, Ah_ + (size_t)(m0 + r_) * KDIM + soA_);                 \
        }                                                                    \
    } while (0)

#define LDG_A32(ch, pf) do {                                                 \
        const float* Af_ = (const float*)Ap;                                 \
        size_t soA_ = (size_t)((ch) * 64) + ckc * 8;                         \
        _Pragma("unroll")                                                    \
        for (int u = 0; u < 4; u++) {                                        \
            int r_ = cr0 + u * 32;                                           \
            const float4* s4_ = (const float4*)(Af_ + (size_t)(m0 + r_) * KDIM + soA_); \
            (pf)[u][0] = s4_[0];                                             \
            (pf)[u][1] = s4_[1];                                             \
        }                                                                    \
    } while (0)

#define STS_A32(st, pf) do {                                                 \
        uint32_t spA_ = sb + (st) * STAGE_BYTES;                             \
        _Pragma("unroll")                                                    \
        for (int u = 0; u < 4; u++) {                                        \
            int r_ = cr0 + u * 32;                                           \
            uint32_t d_ = spA_ + r_ * 128 + (((uint32_t)(ckc ^ (r_ & 7))) << 4); \
            __half2 a_ = __floats2half2_rn((pf)[u][0].x, (pf)[u][0].y);      \
            __half2 b_ = __floats2half2_rn((pf)[u][0].z, (pf)[u][0].w);      \
            __half2 c_ = __floats2half2_rn((pf)[u][1].x, (pf)[u][1].y);      \
            __half2 e_ = __floats2half2_rn((pf)[u][1].z, (pf)[u][1].w);      \
            asm volatile("st.shared.v4.b32 [%0], {%1,%2,%3,%4};"             \
                :: "r"(d_), "r"(*(uint32_t*)&a_), "r"(*(uint32_t*)&b_),      \
                   "r"(*(uint32_t*)&c_), "r"(*(uint32_t*)&e_) : "memory");   \
        }                                                                    \
    } while (0)

    // prologue: stages 0..2
    if (A_FP32) {
        float4 p0[4][2], p1[4][2], p2[4][2];
        LDG_A32(0, p0); LDG_A32(1, p1); LDG_A32(2, p2);
        LOAD_B(0, 0); CP_COMMIT();
        LOAD_B(1, 1); CP_COMMIT();
        LOAD_B(2, 2); CP_COMMIT();
        STS_A32(0, p0); STS_A32(1, p1); STS_A32(2, p2);
    } else {
        LOAD_A16(0, 0); LOAD_B(0, 0); CP_COMMIT();
        LOAD_A16(1, 1); LOAD_B(1, 1); CP_COMMIT();
        LOAD_A16(2, 2); LOAD_B(2, 2); CP_COMMIT();
    }

    float acc[4][8][4];
#pragma unroll
    for (int a = 0; a < 4; a++)
#pragma unroll
        for (int b = 0; b < 8; b++)
#pragma unroll
            for (int c = 0; c < 4; c++) acc[a][b][c] = 0.f;

    const int g  = lane >> 3;
    const int lr = lane & 7;
    const int gh = g >> 1;
    const int lrB = lane & 7, hB = (lane >> 3) & 1;
    const uint32_t aRow = (uint32_t)((warp_m * 64 + (g & 1) * 8 + lr) * 128);
    const uint32_t bRow = (uint32_t)((warp_n * 64 + lrB) * 128);

    for (int c = 0; c < 8; c++) {
        if (c < 6) CP_WAIT2(); else if (c == 6) CP_WAIT1(); else CP_WAIT0();
        __syncthreads();

        float4 pf[4][2];
        if (c + 3 < 8) {
            if (A_FP32) LDG_A32(c + 3, pf);
            else        LOAD_A16((c + 3) & 3, c + 3);
            LOAD_B((c + 3) & 3, c + 3);
            CP_COMMIT();
        }

        const uint32_t As = sb + (c & 3) * STAGE_BYTES;
        const uint32_t Bs = As + 16384;
#pragma unroll
        for (int ks = 0; ks < 4; ks++) {
            uint32_t ah[4][4], bh[8][2];
            const uint32_t cA = (uint32_t)(((ks * 2 + gh) ^ lr) << 4);
            const uint32_t cB = (uint32_t)(((ks * 2 + hB) ^ lrB) << 4);
#pragma unroll
            for (int mi = 0; mi < 4; mi++) LDSM4(ah[mi], As + aRow + mi * 2048 + cA);
#pragma unroll
            for (int ni = 0; ni < 8; ni++) LDSM2(bh[ni], Bs + bRow + ni * 1024 + cB);
#pragma unroll
            for (int mi = 0; mi < 4; mi++)
#pragma unroll
                for (int ni = 0; ni < 8; ni++) MMA16816(acc[mi][ni], ah[mi], bh[ni]);
        }

        if (A_FP32 && c + 3 < 8) STS_A32((c + 3) & 3, pf);
    }

    const int rbase = m0 + warp_m * 64 + (lane >> 2);
    const int cbase = n0 + warp_n * 64 + (lane & 3) * 2;
    if (out_mode == 0) {
        float* C = (float*)Cv;
#pragma unroll
        for (int mi = 0; mi < 4; mi++)
#pragma unroll
            for (int ni = 0; ni < 8; ni++) {
                int cc = cbase + ni * 8;
                float b0 = bias[cc], b1 = bias[cc + 1];
                int r0 = rbase + mi * 16;
                *(float2*)(C + (size_t)r0 * N + cc) =
                    make_float2(acc[mi][ni][0] + b0, acc[mi][ni][1] + b1);
                *(float2*)(C + (size_t)(r0 + 8) * N + cc) =
                    make_float2(acc[mi][ni][2] + b0, acc[mi][ni][3] + b1);
            }
    } else {
        __half* C = (__half*)Cv;
#pragma unroll
        for (int mi = 0; mi < 4; mi++)
#pragma unroll
            for (int ni = 0; ni < 8; ni++) {
                int cc = cbase + ni * 8;
                // q columns carry hd^-0.5 * log2e (attention works in log2 domain)
                const float s = (cc < 512) ? (0.17677669529663687f * 1.4426950408889634f) : 1.0f;
                float b0 = bias[cc], b1 = bias[cc + 1];
                int r0 = rbase + mi * 16;
                __half2 w0 = __floats2half2_rn((acc[mi][ni][0] + b0) * s, (acc[mi][ni][1] + b1) * s);
                __half2 w1 = __floats2half2_rn((acc[mi][ni][2] + b0) * s, (acc[mi][ni][3] + b1) * s);
                *(__half2*)(C + (size_t)r0 * N + cc) = w0;
                *(__half2*)(C + (size_t)(r0 + 8) * N + cc) = w1;
            }
    }
#undef LOAD_B
#undef LOAD_A16
#undef LDG_A32
#undef STS_A32
}

// ---------------- tensor-core fused window attention --------------------------
// block: one window x 2 heads; 8 warps; warp = (head hh, m-tile mi)
// softmax in log2 domain via ex2.approx.f16x2; row sums via ones-column of V.
__global__ __launch_bounds__(256) void attn_tc(
    const __half* __restrict__ qkv, const __half* __restrict__ comb2,
    __half* __restrict__ outh)
{
    __shared__ __align__(16) __half sQ[2][64][40];
    __shared__ __align__(16) __half sK[2][64][40];
    __shared__ __align__(16) __half sVt[2][40][72];   // dims 0-31 = V^T, dim 32 = ones

    const int b = blockIdx.x;
    const int h0 = blockIdx.y * 2;
    const int tid = threadIdx.x;
    const int lane = tid & 31, wid = tid >> 5;

    // load Q, K via float4 (8 halves each)
#pragma unroll
    for (int u = 0; u < 4; u++) {
        int i = tid + u * 256;                 // 1024 items
        int d4 = i & 3, row = (i >> 2) & 63, mat = (i >> 8) & 1, hh = i >> 9;
        uint4 v = make_uint4(0u, 0u, 0u, 0u);
        if (row < SS)
            v = *(const uint4*)(qkv + (size_t)(b * SS + row) * QKV_N
                                + mat * 512 + (h0 + hh) * HD + d4 * 8);
        if (mat == 0) *(uint4*)&sQ[hh][row][d4 * 8] = v;
        else          *(uint4*)&sK[hh][row][d4 * 8] = v;
    }
    // load V via float4, transpose into sVt[hh][dim][token]
#pragma unroll
    for (int u = 0; u < 2; u++) {
        int i = tid + u * 256;                 // 512 items
        int d4 = i & 3, row = (i >> 2) & 63, hh = i >> 8;
        uint4 v = make_uint4(0u, 0u, 0u, 0u);
        if (row < SS)
            v = *(const uint4*)(qkv + (size_t)(b * SS + row) * QKV_N
                                + 1024 + (h0 + hh) * HD + d4 * 8);
        const __half* hp = (const __half*)&v;
#pragma unroll
        for (int j = 0; j < 8; j++)
            sVt[hh][d4 * 8 + j][row] = hp[j];
    }
    // ones-column rows (dims 32..39): dim 32 = 1, rest 0
#pragma unroll
    for (int u = 0; u < 4; u++) {
        int i = tid + u * 256;                 // 1024 items
        int tok = i & 63, d = (i >> 6) & 7, hh = i >> 9;
        sVt[hh][32 + d][tok] = (d == 0) ? __float2half(1.f) : __ushort_as_half(0);
    }
    __syncthreads();

    const int hh = wid >> 2;
    const int mi = wid & 3;
    const int h  = h0 + hh;
    const int lr = lane & 7;
    const int grp = lane >> 3;
    const int khalf = (lane >> 3) & 1;

    // Q A-fragments (2 k16 tiles)
    uint32_t aq[2][4];
    {
        int arow = mi * 16 + (grp & 1) * 8 + lr;
        int acol = (grp >> 1) * 8;
        LDSM4(aq[0], smem_u32(&sQ[hh][arow][acol]));
        LDSM4(aq[1], smem_u32(&sQ[hh][arow][16 + acol]));
    }

    // S = Q K^T  (7 n-tiles), logits in log2 units (q pre-scaled)
    float sacc[7][4];
#pragma unroll
    for (int n = 0; n < 7; n++)
#pragma unroll
        for (int e = 0; e < 4; e++) sacc[n][e] = 0.f;

#pragma unroll
    for (int n = 0; n < 7; n++) {
        int brow = n * 8 + lr;
#pragma unroll
        for (int kt = 0; kt < 2; kt++) {
            uint32_t bk[2];
            LDSM2(bk, smem_u32(&sK[hh][brow][kt * 16 + khalf * 8]));
            MMA16816(sacc[n], aq[kt], bk);
        }
    }

    // add comb (already log2-scaled)
    const int wg = b & (NWG - 1);
    const __half* cbp = comb2 + (size_t)(wg * NHEADS + h) * 64 * 56;
    const int r0 = mi * 16 + (lane >> 2);
    const int c0 = (lane & 3) * 2;
#pragma unroll
    for (int n = 0; n < 7; n++) {
        __half2 cv0 = *(const __half2*)(cbp + r0 * 56 + n * 8 + c0);
        __half2 cv1 = *(const __half2*)(cbp + (r0 + 8) * 56 + n * 8 + c0);
        float2 f0 = __half22float2(cv0), f1 = __half22float2(cv1);
        sacc[n][0] += f0.x;
        sacc[n][1] += f0.y;
        sacc[n][2] += f1.x;
        sacc[n][3] += f1.y;
    }

    // P -> A fragments directly (unnormalized exps in fp16)
    uint32_t pa[4][4];
#pragma unroll
    for (int t = 0; t < 3; t++) {
        EX2F16X2(pa[t][0], h2u(sacc[2 * t][0],     sacc[2 * t][1]));
        EX2F16X2(pa[t][1], h2u(sacc[2 * t][2],     sacc[2 * t][3]));
        EX2F16X2(pa[t][2], h2u(sacc[2 * t + 1][0], sacc[2 * t + 1][1]));
        EX2F16X2(pa[t][3], h2u(sacc[2 * t + 1][2], sacc[2 * t + 1][3]));
    }
    EX2F16X2(pa[3][0], h2u(sacc[6][0], sacc[6][1]));
    EX2F16X2(pa[3][1], h2u(sacc[6][2], sacc[6][3]));
    pa[3][2] = 0u;
    pa[3][3] = 0u;

    // O = P V  (nv=4 tile holds the ones-column -> row sums in col 32)
    float oacc[5][4];
#pragma unroll
    for (int nv = 0; nv < 5; nv++)
#pragma unroll
        for (int e = 0; e < 4; e++) oacc[nv][e] = 0.f;

#pragma unroll
    for (int t = 0; t < 4; t++)
#pragma unroll
        for (int nv = 0; nv < 5; nv++) {
            uint32_t bv[2];
            LDSM2(bv, smem_u32(&sVt[hh][nv * 8 + lr][t * 16 + khalf * 8]));
            MMA16816(oacc[nv], pa[t], bv);
        }

    // row sums live in col 32 -> quad leader's oacc[4][0]/[2]
    const float rsA = __shfl_sync(0xffffffffu, oacc[4][0], lane & ~3);
    const float rsB = __shfl_sync(0xffffffffu, oacc[4][2], lane & ~3);
    const float inv0 = 1.f / (rsA + 1e-30f);
    const float inv1 = 1.f / (rsB + 1e-30f);

    // store fp16 rows < 49
#pragma unroll
    for (int nv = 0; nv < 4; nv++) {
        int col = h * HD + nv * 8 + c0;
        if (r0 < SS) {
            __half2 w = __floats2half2_rn(oacc[nv][0] * inv0, oacc[nv][1] * inv0);
            *(__half2*)(outh + (size_t)(b * SS + r0) * DIMC + col) = w;
        }
        if (r0 + 8 < SS) {
            __half2 w = __floats2half2_rn(oacc[nv][2] * inv1, oacc[nv][3] * inv1);
            *(__half2*)(outh + (size_t)(b * SS + r0 + 8) * DIMC + col) = w;
        }
    }
}

// ---------------- launch ------------------------------------------------------
extern "C" void kernel_launch(void* const* d_in, const int* in_sizes, int n_in,
                              void* d_out, int out_size)
{
    const float* x          = (const float*)d_in[0];
    const float* mask       = (const float*)d_in[1];
    const float* Wqkv       = (const float*)d_in[2];
    const float* bqkv       = (const float*)d_in[3];
    const float* Wproj      = (const float*)d_in[4];
    const float* bproj      = (const float*)d_in[5];
    const float* bias_table = (const float*)d_in[6];
    const int*   rel_index  = (const int*)d_in[7];
    float* out = (float*)d_out;

    __half *qkvh, *xh, *wqh, *wph, *comb2;
    cudaGetSymbolAddress((void**)&qkvh,  g_qkvh);
    cudaGetSymbolAddress((void**)&xh,    g_xh);
    cudaGetSymbolAddress((void**)&wqh,   g_wqh);
    cudaGetSymbolAddress((void**)&wph,   g_wph);
    cudaGetSymbolAddress((void**)&comb2, g_comb2);

    cudaFuncSetAttribute(gemm_hmma<1>, cudaFuncAttributeMaxDynamicSharedMemorySize, GEMM_SMEM);
    cudaFuncSetAttribute(gemm_hmma<0>, cudaFuncAttributeMaxDynamicSharedMemorySize, GEMM_SMEM);

    // order: gemm1 is the 4th launch (profiled slot)
    conv_w<<<(KDIM * QKV_N + 255) / 256, 256>>>(Wqkv, wqh, KDIM, QKV_N);
    comb_k<<<(NWG * NHEADS * 64 * 56 + 255) / 256, 256>>>(mask, bias_table, rel_index, comb2);
    conv_w<<<(KDIM * DIMC  + 255) / 256, 256>>>(Wproj, wph, KDIM, DIMC);

    gemm_hmma<1><<<dim3(QKV_N / 256, TOKENS / 128), 256, GEMM_SMEM>>>(
        (const void*)x, wqh, bqkv, qkvh, QKV_N, 1);

    attn_tc<<<dim3(4096, 8), 256>>>(qkvh, comb2, xh);

    gemm_hmma<0><<<dim3(DIMC / 256, TOKENS / 128), 256, GEMM_SMEM>>>(
        (const void*)xh, wph, bproj, out, DIMC, 0);
}